// round 2
// baseline (speedup 1.0000x reference)
#include <cuda_runtime.h>

// SimpleMLP via fused FFT-butterfly network.
// N = 4096 complex per row, 12 radix-2 stages per layer, 2 layers, ReLU between.
// One CTA per batch row; whole row lives in shared memory.

#define N_FFT    4096
#define LOG2N    12
#define HALF_N   2048
#define BATCH    4096
#define OUT_C    1024            // output complex elements per row
#define NTHREADS 512

// Precomputed twiddles: tw[k] = exp(-2*pi*i/N * k * w[k]), k in [0, 2048)
__device__ float2 g_tw1[HALF_N];
__device__ float2 g_tw2[HALF_N];

__global__ void twiddle_kernel(const float* __restrict__ w1,
                               const float* __restrict__ w2) {
    int k = blockIdx.x * blockDim.x + threadIdx.x;
    if (k < HALF_N) {
        const float c = -6.283185307179586f / (float)N_FFT;
        float kk = (float)k;
        float a1 = c * kk * w1[k];
        float a2 = c * kk * w2[k];
        float s, co;
        sincosf(a1, &s, &co);
        g_tw1[k] = make_float2(co, s);
        sincosf(a2, &s, &co);
        g_tw2[k] = make_float2(co, s);
    }
}

__device__ __forceinline__ void butterfly_stages(float2* X, const float2* TW, int t) {
    #pragma unroll 1
    for (int s = 1; s <= LOG2N; s++) {
        const int half  = 1 << (s - 1);
        const int shift = LOG2N - s;
        #pragma unroll
        for (int u = 0; u < HALF_N / NTHREADS; u++) {
            int b = t + u * NTHREADS;
            int j = b & (half - 1);
            int i = ((b ^ j) << 1) | j;     // group*step + j
            float2 a  = X[i];
            float2 bb = X[i + half];
            float2 tw = TW[j << shift];
            // tt = tw * bb (complex multiply)
            float2 tt;
            tt.x = tw.x * bb.x - tw.y * bb.y;
            tt.y = tw.x * bb.y + tw.y * bb.x;
            X[i]        = make_float2(a.x + tt.x, a.y + tt.y);
            X[i + half] = make_float2(a.x - tt.x, a.y - tt.y);
        }
        __syncthreads();
    }
}

__global__ __launch_bounds__(NTHREADS)
void mlp_fft_kernel(const float2* __restrict__ xin, float2* __restrict__ out) {
    extern __shared__ float2 smem[];
    float2* X  = smem;           // N_FFT   complex
    float2* TW = smem + N_FFT;   // HALF_N  complex (reused between layers)

    const int row = blockIdx.x;
    const int t   = threadIdx.x;
    const float2* xrow = xin + (size_t)row * N_FFT;

    // ---- Layer 1: load with XOR-half permutation; stage twiddles 1 ----
    #pragma unroll
    for (int u = 0; u < N_FFT / NTHREADS; u++) {
        int j = t + u * NTHREADS;
        X[j] = xrow[j ^ HALF_N];
    }
    #pragma unroll
    for (int u = 0; u < HALF_N / NTHREADS; u++) {
        int j = t + u * NTHREADS;
        TW[j] = g_tw1[j];
    }
    __syncthreads();

    butterfly_stages(X, TW, t);

    // ---- ReLU (on real & imag independently) + XOR-half permutation.
    // Each thread owns disjoint pairs (j, j+HALF_N): no cross-thread hazard.
    #pragma unroll
    for (int u = 0; u < HALF_N / NTHREADS; u++) {
        int j = t + u * NTHREADS;
        float2 a = X[j];
        float2 b = X[j + HALF_N];
        X[j]          = make_float2(fmaxf(b.x, 0.f), fmaxf(b.y, 0.f));
        X[j + HALF_N] = make_float2(fmaxf(a.x, 0.f), fmaxf(a.y, 0.f));
    }
    // Stage twiddles 2 (overwrites TW; guarded by the sync below)
    #pragma unroll
    for (int u = 0; u < HALF_N / NTHREADS; u++) {
        int j = t + u * NTHREADS;
        TW[j] = g_tw2[j];
    }
    __syncthreads();

    butterfly_stages(X, TW, t);

    // ---- Output: first OUT_C complex values, interleaved re/im == float2 ----
    #pragma unroll
    for (int u = 0; u < OUT_C / NTHREADS; u++) {
        int j = t + u * NTHREADS;
        out[(size_t)row * OUT_C + j] = X[j];
    }
}

extern "C" void kernel_launch(void* const* d_in, const int* in_sizes, int n_in,
                              void* d_out, int out_size) {
    const float* x  = (const float*)d_in[0];   // (4096, 8192) f32
    const float* w1 = (const float*)d_in[1];   // (2048,) f32
    const float* w2 = (const float*)d_in[2];   // (2048,) f32
    float* out = (float*)d_out;                // (4096, 2048) f32

    twiddle_kernel<<<2, 1024>>>(w1, w2);

    const int smem_bytes = (N_FFT + HALF_N) * sizeof(float2);  // 48 KB
    mlp_fft_kernel<<<BATCH, NTHREADS, smem_bytes>>>(
        (const float2*)x, (float2*)out);
}

// round 4
// speedup vs baseline: 2.0552x; 2.0552x over previous
#include <cuda_runtime.h>

// Fused FFT-butterfly MLP, register-resident butterflies.
// N=4096 complex/row, 12 radix-2 stages x 2 layers, ReLU+perm between.
// One CTA (512 thr) per row; each thread owns 8 complex values in registers.
// Stages 1-3: register bits. Stages 4-8: lane bits via shfl_xor.
// One smem exchange; stage 9 via shfl, stages 10-12 register bits.

#define N_FFT    4096
#define HALF_N   2048
#define BATCH    4096
#define OUT_C    1024
#define NT       512

// Padded smem geometry (in float2 units)
#define DATA_F2  4608              // 4096 + 512 pad  (pad: i + (i>>3))
#define TW_F2    2176              // 2048 + 128 pad  (pad: k + (k>>4))
#define SMEM_BYTES ((DATA_F2 + TW_F2) * (int)sizeof(float2))   // 54272

__device__ float2 g_tw1[HALF_N];
__device__ float2 g_tw2[HALF_N];

__global__ void twiddle_kernel(const float* __restrict__ w1,
                               const float* __restrict__ w2) {
    int k = blockIdx.x * blockDim.x + threadIdx.x;
    if (k < HALF_N) {
        const float c = -6.283185307179586f / (float)N_FFT;
        float kk = (float)k;
        float s, co;
        sincosf(c * kk * w1[k], &s, &co);
        g_tw1[k] = make_float2(co, s);
        sincosf(c * kk * w2[k], &s, &co);
        g_tw2[k] = make_float2(co, s);
    }
}

__device__ __forceinline__ int padD(int i) { return i + (i >> 3); }
__device__ __forceinline__ int padT(int k) { return k + (k >> 4); }

__device__ __forceinline__ float2 cmul(float2 a, float2 b) {
    return make_float2(a.x * b.x - a.y * b.y, a.x * b.y + a.y * b.x);
}

// butterfly: a' = a + tw*b ; b' = a - tw*b
__device__ __forceinline__ void bf(float2& a, float2& b, float2 tw) {
    float2 t = cmul(tw, b);
    float2 na = make_float2(a.x + t.x, a.y + t.y);
    b = make_float2(a.x - t.x, a.y - t.y);
    a = na;
}
__device__ __forceinline__ void bf1(float2& a, float2& b) {  // tw = 1
    float2 na = make_float2(a.x + b.x, a.y + b.y);
    b = make_float2(a.x - b.x, a.y - b.y);
    a = na;
}

// Shuffle butterfly stage: stage bit lives in lane bit log2(mask).
// k(r) = (jbase + r) << shift  (jbase from lane low bits; r = register idx 0..7)
__device__ __forceinline__ void shfl_stage(float2* X, int lane, const float2* TW,
                                           int mask, int jbase, int shift) {
    bool up = (lane & mask) != 0;
    #pragma unroll
    for (int r = 0; r < 8; r++) {
        float2 v = X[r];
        float2 p;
        p.x = __shfl_xor_sync(0xffffffffu, v.x, mask);
        p.y = __shfl_xor_sync(0xffffffffu, v.y, mask);
        float2 tw = TW[padT((jbase + r) << shift)];
        if (up) {               // own = b, partner = a : result = a - tw*b
            float2 tb = cmul(tw, v);
            X[r] = make_float2(p.x - tb.x, p.y - tb.y);
        } else {                // own = a, partner = b : result = a + tw*b
            float2 tb = cmul(tw, p);
            X[r] = make_float2(v.x + tb.x, v.y + tb.y);
        }
    }
}

// Stages 1-8 on A-layout registers (i = 8t + r).
__device__ __forceinline__ void stages_1_8(float2* X, int lane, const float2* TW) {
    // S1: bit 0, tw = 1
    bf1(X[0], X[1]); bf1(X[2], X[3]); bf1(X[4], X[5]); bf1(X[6], X[7]);
    // S2: bit 1, k = (r&1)<<10
    {
        float2 tA = TW[padT(0)];        // = 1
        float2 tB = TW[padT(1 << 10)];
        bf(X[0], X[2], tA); bf(X[1], X[3], tB);
        bf(X[4], X[6], tA); bf(X[5], X[7], tB);
    }
    // S3: bit 2, k = (r&3)<<9
    {
        bf(X[0], X[4], TW[padT(0 << 9)]);
        bf(X[1], X[5], TW[padT(1 << 9)]);
        bf(X[2], X[6], TW[padT(2 << 9)]);
        bf(X[3], X[7], TW[padT(3 << 9)]);
    }
    // S4..S8: lane bits 0..4 ; jbase = (lane & (mask-1)) << 3 ; shift = 12 - s
    shfl_stage(X, lane, TW, 1,  (lane & 0)  << 3, 8);
    shfl_stage(X, lane, TW, 2,  (lane & 1)  << 3, 7);
    shfl_stage(X, lane, TW, 4,  (lane & 3)  << 3, 6);
    shfl_stage(X, lane, TW, 8,  (lane & 7)  << 3, 5);
    shfl_stage(X, lane, TW, 16, (lane & 15) << 3, 4);
}

// Stages 9-12 on D-layout registers (i = tid9 | (r<<9); tid9 bit 8 = lane bit 0).
__device__ __forceinline__ void stages_9_12(float2* X, int lane, int tid9,
                                            const float2* TW) {
    // S9: bit 8 = lane bit 0 ; k = (i & 255) << 3, uniform over r
    {
        bool up = (lane & 1) != 0;
        float2 tw = TW[padT((tid9 & 255) << 3)];
        #pragma unroll
        for (int r = 0; r < 8; r++) {
            float2 v = X[r];
            float2 p;
            p.x = __shfl_xor_sync(0xffffffffu, v.x, 1);
            p.y = __shfl_xor_sync(0xffffffffu, v.y, 1);
            if (up) { float2 tb = cmul(tw, v); X[r] = make_float2(p.x - tb.x, p.y - tb.y); }
            else    { float2 tb = cmul(tw, p); X[r] = make_float2(v.x + tb.x, v.y + tb.y); }
        }
    }
    // S10: bit 9 = r bit 0 ; k = tid9<<2
    {
        float2 tw = TW[padT(tid9 << 2)];
        bf(X[0], X[1], tw); bf(X[2], X[3], tw); bf(X[4], X[5], tw); bf(X[6], X[7], tw);
    }
    // S11: bit 10 = r bit 1 ; k = (tid9 | (r&1)<<9) << 1
    {
        float2 tA = TW[padT(tid9 << 1)];
        float2 tB = TW[padT((tid9 | 512) << 1)];
        bf(X[0], X[2], tA); bf(X[1], X[3], tB);
        bf(X[4], X[6], tA); bf(X[5], X[7], tB);
    }
    // S12: bit 11 = r bit 2 ; k = tid9 | (r&3)<<9
    {
        bf(X[0], X[4], TW[padT(tid9)]);
        bf(X[1], X[5], TW[padT(tid9 | (1 << 9))]);
        bf(X[2], X[6], TW[padT(tid9 | (2 << 9))]);
        bf(X[3], X[7], TW[padT(tid9 | (3 << 9))]);
    }
}

__global__ __launch_bounds__(NT, 3)
void mlp_fft_kernel(const float2* __restrict__ xin, float2* __restrict__ out) {
    extern __shared__ float2 sm[];
    float2* SD = sm;             // DATA_F2
    float2* TW = sm + DATA_F2;   // TW_F2

    const int t    = threadIdx.x;
    const int lane = t & 31;
    const int w    = t >> 5;
    const int tid9 = (w << 4) | (lane >> 1) | ((lane & 1) << 8);
    const int row  = blockIdx.x;

    float2 X[8];

    // --- Stage twiddles 1 into smem; load input (A-layout, perm ^2048) ---
    #pragma unroll
    for (int u = 0; u < 4; u++) {
        int k = t + u * NT;
        TW[padT(k)] = g_tw1[k];
    }
    {
        const float4* xr4 = (const float4*)(xin + (size_t)row * N_FFT);
        #pragma unroll
        for (int c = 0; c < 4; c++) {
            float4 v = __ldg(&xr4[(4 * t + c) ^ 1024]);   // ^2048 in float2 idx
            X[2 * c]     = make_float2(v.x, v.y);
            X[2 * c + 1] = make_float2(v.z, v.w);
        }
    }
    __syncthreads();   // TW1 ready

    // ================= Layer 1 =================
    stages_1_8(X, lane, TW);

    // Exchange A -> D (first SD use: no pre-write sync needed)
    #pragma unroll
    for (int r = 0; r < 8; r++) SD[padD(8 * t + r)] = X[r];
    __syncthreads();
    #pragma unroll
    for (int r = 0; r < 8; r++) X[r] = SD[padD(tid9 | (r << 9))];

    stages_9_12(X, lane, tid9, TW);

    // ReLU + perm (^2048 flips r bit 2): register-local
    {
        float2 Y[8];
        #pragma unroll
        for (int r = 0; r < 8; r++) {
            float2 v = X[r ^ 4];
            Y[r] = make_float2(fmaxf(v.x, 0.f), fmaxf(v.y, 0.f));
        }
        #pragma unroll
        for (int r = 0; r < 8; r++) X[r] = Y[r];
    }

    // Exchange D -> A, swap twiddle table to layer 2
    __syncthreads();   // prior SD/TW readers done
    #pragma unroll
    for (int r = 0; r < 8; r++) SD[padD(tid9 | (r << 9))] = X[r];
    #pragma unroll
    for (int u = 0; u < 4; u++) {
        int k = t + u * NT;
        TW[padT(k)] = g_tw2[k];
    }
    __syncthreads();
    #pragma unroll
    for (int r = 0; r < 8; r++) X[r] = SD[padD(8 * t + r)];

    // ================= Layer 2 =================
    stages_1_8(X, lane, TW);

    // Exchange A -> D
    __syncthreads();   // prior A-layout readers done
    #pragma unroll
    for (int r = 0; r < 8; r++) SD[padD(8 * t + r)] = X[r];
    __syncthreads();
    #pragma unroll
    for (int r = 0; r < 8; r++) X[r] = SD[padD(tid9 | (r << 9))];

    stages_9_12(X, lane, tid9, TW);

    // Output: first OUT_C complex = indices with r in {0,1}
    out[(size_t)row * OUT_C + tid9]       = X[0];
    out[(size_t)row * OUT_C + tid9 + 512] = X[1];
}

extern "C" void kernel_launch(void* const* d_in, const int* in_sizes, int n_in,
                              void* d_out, int out_size) {
    const float* x  = (const float*)d_in[0];   // (4096, 8192) f32
    const float* w1 = (const float*)d_in[1];   // (2048,) f32
    const float* w2 = (const float*)d_in[2];   // (2048,) f32
    float* out = (float*)d_out;                // (4096, 2048) f32

    cudaFuncSetAttribute(mlp_fft_kernel,
                         cudaFuncAttributeMaxDynamicSharedMemorySize, SMEM_BYTES);

    twiddle_kernel<<<2, 1024>>>(w1, w2);
    mlp_fft_kernel<<<BATCH, NT, SMEM_BYTES>>>((const float2*)x, (float2*)out);
}

// round 5
// speedup vs baseline: 3.8631x; 1.8797x over previous
#include <cuda_runtime.h>

// Fused FFT-butterfly MLP, register-resident butterflies.
// N=4096 complex/row, 12 radix-2 stages x 2 layers, ReLU+perm between.
// One CTA (512 thr) per row; each thread owns 8 complex values in registers.
// Stages 1-3: register bits. Stages 4-8: lane-bit<->register-bit SWAPS (8 SHFL)
// followed by register-local butterflies (4 cmul, computed once per pair).
// The induced index-bit permutation is folded into the A->D smem exchange.
// Stage 9 via broadcast-twiddle shuffle; stages 10-12 register bits.

#define N_FFT    4096
#define HALF_N   2048
#define BATCH    4096
#define OUT_C    1024
#define NT       512

// Padded smem geometry (in float2 units)
#define DATA_F2  4608              // 4096 + 512 pad  (pad: i + (i>>3))
#define TW_F2    2176              // 2048 + 128 pad  (pad: k + (k>>4))
#define SMEM_BYTES ((DATA_F2 + TW_F2) * (int)sizeof(float2))   // 54272

__device__ float2 g_tw1[HALF_N];
__device__ float2 g_tw2[HALF_N];

__global__ void twiddle_kernel(const float* __restrict__ w1,
                               const float* __restrict__ w2) {
    int k = blockIdx.x * blockDim.x + threadIdx.x;
    if (k < HALF_N) {
        const float c = -6.283185307179586f / (float)N_FFT;
        float kk = (float)k;
        float s, co;
        sincosf(c * kk * w1[k], &s, &co);
        g_tw1[k] = make_float2(co, s);
        sincosf(c * kk * w2[k], &s, &co);
        g_tw2[k] = make_float2(co, s);
    }
}

__device__ __forceinline__ int padD(int i) { return i + (i >> 3); }
__device__ __forceinline__ int padT(int k) { return k + (k >> 4); }

__device__ __forceinline__ float2 cmul(float2 a, float2 b) {
    return make_float2(a.x * b.x - a.y * b.y, a.x * b.y + a.y * b.x);
}

// butterfly: a' = a + tw*b ; b' = a - tw*b
__device__ __forceinline__ void bf(float2& a, float2& b, float2 tw) {
    float2 t = cmul(tw, b);
    float2 na = make_float2(a.x + t.x, a.y + t.y);
    b = make_float2(a.x - t.x, a.y - t.y);
    a = na;
}
__device__ __forceinline__ void bf1(float2& a, float2& b) {  // tw = 1
    float2 na = make_float2(a.x + b.x, a.y + b.y);
    b = make_float2(a.x - b.x, a.y - b.y);
    a = na;
}

// Swap lane bit m with register bit rho (index-bit transpose).
// Elements whose lane-m bit equals their reg-rho bit stay; the other half
// cross the lane pair. 4 register pairs -> 8 SHFL.b32 total.
__device__ __forceinline__ void swap_lr(float2* X, int lane, int m, int rho) {
    bool hi = (lane & m) != 0;
    #pragma unroll
    for (int n = 0; n < 8; n++) {
        if (n & rho) continue;           // visit each (nlo, nhi) pair once
        int nh = n | rho;
        float2 send = hi ? X[n] : X[nh];
        send.x = __shfl_xor_sync(0xffffffffu, send.x, m);
        send.y = __shfl_xor_sync(0xffffffffu, send.y, m);
        if (hi) X[n] = send; else X[nh] = send;
    }
}

// Stages 1-8. Input: A layout (i = 8t + r). Output layout (tracked, folded
// into the exchange store): lanes l0..l4 = i0..i4, regs r0,r1,r2 = i6,i7,i5.
__device__ __forceinline__ void stages_1_8(float2* X, int lane, const float2* TW) {
    // S1: bit 0, tw = 1
    bf1(X[0], X[1]); bf1(X[2], X[3]); bf1(X[4], X[5]); bf1(X[6], X[7]);
    // S2: bit 1, k = (r&1)<<10
    {
        float2 tA = TW[padT(0)];        // = 1
        float2 tB = TW[padT(1 << 10)];
        bf(X[0], X[2], tA); bf(X[1], X[3], tB);
        bf(X[4], X[6], tA); bf(X[5], X[7], tB);
    }
    // S3: bit 2, k = (r&3)<<9
    {
        bf(X[0], X[4], TW[padT(0 << 9)]);
        bf(X[1], X[5], TW[padT(1 << 9)]);
        bf(X[2], X[6], TW[padT(2 << 9)]);
        bf(X[3], X[7], TW[padT(3 << 9)]);
    }
    // S4: swap(l0, reg bit0); work bit i3 at reg bit0. j = l0 + 2*i1 + 4*i2
    {
        swap_lr(X, lane, 1, 1);
        int l0 = lane & 1;
        bf(X[0], X[1], TW[padT((l0 + 0) << 8)]);
        bf(X[2], X[3], TW[padT((l0 + 2) << 8)]);
        bf(X[4], X[5], TW[padT((l0 + 4) << 8)]);
        bf(X[6], X[7], TW[padT((l0 + 6) << 8)]);
    }
    // S5: swap(l1, reg bit1); work bit i4 at reg bit1.
    // j = (lane&3) + 4*i2(regbit2) + 8*i3(regbit0)
    {
        swap_lr(X, lane, 2, 2);
        int l01 = lane & 3;
        bf(X[0], X[2], TW[padT((l01 + 0)  << 7)]);
        bf(X[1], X[3], TW[padT((l01 + 8)  << 7)]);
        bf(X[4], X[6], TW[padT((l01 + 4)  << 7)]);
        bf(X[5], X[7], TW[padT((l01 + 12) << 7)]);
    }
    // S6: swap(l2, reg bit2); work bit i5 at reg bit2.
    // j = (lane&7) + 8*i3(regbit0) + 16*i4(regbit1)
    {
        swap_lr(X, lane, 4, 4);
        int l02 = lane & 7;
        bf(X[0], X[4], TW[padT((l02 + 0)  << 6)]);
        bf(X[1], X[5], TW[padT((l02 + 8)  << 6)]);
        bf(X[2], X[6], TW[padT((l02 + 16) << 6)]);
        bf(X[3], X[7], TW[padT((l02 + 24) << 6)]);
    }
    // S7: swap(l3, reg bit0); work bit i6 at reg bit0 (l3 now holds i3).
    // j = (lane&15) + 16*i4(regbit1) + 32*i5(regbit2)
    {
        swap_lr(X, lane, 8, 1);
        int l03 = lane & 15;
        bf(X[0], X[1], TW[padT((l03 + 0)  << 5)]);
        bf(X[2], X[3], TW[padT((l03 + 16) << 5)]);
        bf(X[4], X[5], TW[padT((l03 + 32) << 5)]);
        bf(X[6], X[7], TW[padT((l03 + 48) << 5)]);
    }
    // S8: swap(l4, reg bit1); work bit i7 at reg bit1 (l4 now holds i4).
    // j = lane + 32*i5(regbit2) + 64*i6(regbit0)
    {
        swap_lr(X, lane, 16, 2);
        bf(X[0], X[2], TW[padT((lane + 0)  << 4)]);
        bf(X[1], X[3], TW[padT((lane + 64) << 4)]);
        bf(X[4], X[6], TW[padT((lane + 32) << 4)]);
        bf(X[5], X[7], TW[padT((lane + 96) << 4)]);
    }
}

// True element index of register n after stages_1_8:
// i = lane + 32*c(n) + 256*w, with c(n) = i5 + 2*i6 + 4*i7
//   = ((n>>2)&1) + 2*(n&1) + 4*((n>>1)&1)
__device__ __forceinline__ int cmap(int n) {
    return ((n >> 2) & 1) + 2 * (n & 1) + 4 * ((n >> 1) & 1);
}

// Stages 9-12 on D-layout registers (i = tid9 | (r<<9); tid9 bit 8 = lane bit 0).
__device__ __forceinline__ void stages_9_12(float2* X, int lane, int tid9,
                                            const float2* TW) {
    // S9: bit 8 = lane bit 0 ; k = (i & 255) << 3, uniform over r
    {
        bool up = (lane & 1) != 0;
        float2 tw = TW[padT((tid9 & 255) << 3)];
        #pragma unroll
        for (int r = 0; r < 8; r++) {
            float2 v = X[r];
            float2 p;
            p.x = __shfl_xor_sync(0xffffffffu, v.x, 1);
            p.y = __shfl_xor_sync(0xffffffffu, v.y, 1);
            if (up) { float2 tb = cmul(tw, v); X[r] = make_float2(p.x - tb.x, p.y - tb.y); }
            else    { float2 tb = cmul(tw, p); X[r] = make_float2(v.x + tb.x, v.y + tb.y); }
        }
    }
    // S10: bit 9 = r bit 0 ; k = tid9<<2
    {
        float2 tw = TW[padT(tid9 << 2)];
        bf(X[0], X[1], tw); bf(X[2], X[3], tw); bf(X[4], X[5], tw); bf(X[6], X[7], tw);
    }
    // S11: bit 10 = r bit 1 ; k = (tid9 | (r&1)<<9) << 1
    {
        float2 tA = TW[padT(tid9 << 1)];
        float2 tB = TW[padT((tid9 | 512) << 1)];
        bf(X[0], X[2], tA); bf(X[1], X[3], tB);
        bf(X[4], X[6], tA); bf(X[5], X[7], tB);
    }
    // S12: bit 11 = r bit 2 ; k = tid9 | (r&3)<<9
    {
        bf(X[0], X[4], TW[padT(tid9)]);
        bf(X[1], X[5], TW[padT(tid9 | (1 << 9))]);
        bf(X[2], X[6], TW[padT(tid9 | (2 << 9))]);
        bf(X[3], X[7], TW[padT(tid9 | (3 << 9))]);
    }
}

__global__ __launch_bounds__(NT, 3)
void mlp_fft_kernel(const float2* __restrict__ xin, float2* __restrict__ out) {
    extern __shared__ float2 sm[];
    float2* SD = sm;             // DATA_F2
    float2* TW = sm + DATA_F2;   // TW_F2

    const int t    = threadIdx.x;
    const int lane = t & 31;
    const int w    = t >> 5;
    const int tid9 = (w << 4) | (lane >> 1) | ((lane & 1) << 8);
    const int row  = blockIdx.x;

    float2 X[8];

    // --- Stage twiddles 1 into smem; load input (A-layout, perm ^2048) ---
    #pragma unroll
    for (int u = 0; u < 4; u++) {
        int k = t + u * NT;
        TW[padT(k)] = g_tw1[k];
    }
    {
        const float4* xr4 = (const float4*)(xin + (size_t)row * N_FFT);
        #pragma unroll
        for (int c = 0; c < 4; c++) {
            float4 v = __ldg(&xr4[(4 * t + c) ^ 1024]);   // ^2048 in float2 idx
            X[2 * c]     = make_float2(v.x, v.y);
            X[2 * c + 1] = make_float2(v.z, v.w);
        }
    }
    __syncthreads();   // TW1 ready

    // ================= Layer 1 =================
    stages_1_8(X, lane, TW);

    // Exchange (permuted A) -> D. Store each register at its TRUE index.
    #pragma unroll
    for (int n = 0; n < 8; n++)
        SD[padD(lane + 32 * cmap(n) + 256 * w)] = X[n];
    __syncthreads();
    #pragma unroll
    for (int r = 0; r < 8; r++) X[r] = SD[padD(tid9 | (r << 9))];

    stages_9_12(X, lane, tid9, TW);

    // ReLU + perm (^2048 flips r bit 2): register-local
    {
        float2 Y[8];
        #pragma unroll
        for (int r = 0; r < 8; r++) {
            float2 v = X[r ^ 4];
            Y[r] = make_float2(fmaxf(v.x, 0.f), fmaxf(v.y, 0.f));
        }
        #pragma unroll
        for (int r = 0; r < 8; r++) X[r] = Y[r];
    }

    // Exchange D -> A, swap twiddle table to layer 2
    __syncthreads();   // prior SD/TW readers done
    #pragma unroll
    for (int r = 0; r < 8; r++) SD[padD(tid9 | (r << 9))] = X[r];
    #pragma unroll
    for (int u = 0; u < 4; u++) {
        int k = t + u * NT;
        TW[padT(k)] = g_tw2[k];
    }
    __syncthreads();
    #pragma unroll
    for (int r = 0; r < 8; r++) X[r] = SD[padD(8 * t + r)];

    // ================= Layer 2 =================
    stages_1_8(X, lane, TW);

    // Exchange (permuted A) -> D
    __syncthreads();   // prior A-layout readers done
    #pragma unroll
    for (int n = 0; n < 8; n++)
        SD[padD(lane + 32 * cmap(n) + 256 * w)] = X[n];
    __syncthreads();
    #pragma unroll
    for (int r = 0; r < 8; r++) X[r] = SD[padD(tid9 | (r << 9))];

    stages_9_12(X, lane, tid9, TW);

    // Output: first OUT_C complex = indices with r in {0,1}
    out[(size_t)row * OUT_C + tid9]       = X[0];
    out[(size_t)row * OUT_C + tid9 + 512] = X[1];
}

extern "C" void kernel_launch(void* const* d_in, const int* in_sizes, int n_in,
                              void* d_out, int out_size) {
    const float* x  = (const float*)d_in[0];   // (4096, 8192) f32
    const float* w1 = (const float*)d_in[1];   // (2048,) f32
    const float* w2 = (const float*)d_in[2];   // (2048,) f32
    float* out = (float*)d_out;                // (4096, 2048) f32

    cudaFuncSetAttribute(mlp_fft_kernel,
                         cudaFuncAttributeMaxDynamicSharedMemorySize, SMEM_BYTES);

    twiddle_kernel<<<2, 1024>>>(w1, w2);
    mlp_fft_kernel<<<BATCH, NT, SMEM_BYTES>>>((const float2*)x, (float2*)out);
}

// round 8
// speedup vs baseline: 4.1497x; 1.0742x over previous
#include <cuda_runtime.h>

// Fused FFT-butterfly MLP, register-resident butterflies, 2 rows per CTA.
// N=4096 complex/row, 12 radix-2 stages x 2 layers, ReLU+perm between.
// One CTA (512 thr) per PAIR of rows; each thread owns 8 complex per row (16 total).
// Twiddle loads are shared across the two rows (halves twiddle wavefronts/row).
// Stages 1-3: register bits. Stages 4-8: lane<->reg bit swaps + local butterflies.
// Stage 9 via broadcast-twiddle shuffle; stages 10-12 register bits.

#define N_FFT    4096
#define HALF_N   2048
#define BATCH    4096
#define OUT_C    1024
#define NT       512

// Padded smem geometry (in float2 units)
#define DATA_F2  4608              // 4096 + 512 pad  (pad: i + (i>>3))
#define TW_F2    2176              // 2048 + 128 pad  (pad: k + (k>>4))
#define SMEM_BYTES ((2 * DATA_F2 + TW_F2) * (int)sizeof(float2))   // 91136

__device__ __align__(16) float2 g_tw1[HALF_N];
__device__ __align__(16) float2 g_tw2[HALF_N];

__global__ void twiddle_kernel(const float* __restrict__ w1,
                               const float* __restrict__ w2) {
    int k = blockIdx.x * blockDim.x + threadIdx.x;
    if (k < HALF_N) {
        const float c = -6.283185307179586f / (float)N_FFT;
        float kk = (float)k;
        float s, co;
        sincosf(c * kk * w1[k], &s, &co);
        g_tw1[k] = make_float2(co, s);
        sincosf(c * kk * w2[k], &s, &co);
        g_tw2[k] = make_float2(co, s);
    }
}

__device__ __forceinline__ int padD(int i) { return i + (i >> 3); }
__device__ __forceinline__ int padT(int k) { return k + (k >> 4); }

__device__ __forceinline__ float2 cmul(float2 a, float2 b) {
    return make_float2(a.x * b.x - a.y * b.y, a.x * b.y + a.y * b.x);
}

// butterfly: a' = a + tw*b ; b' = a - tw*b
__device__ __forceinline__ void bf(float2& a, float2& b, float2 tw) {
    float2 t = cmul(tw, b);
    float2 na = make_float2(a.x + t.x, a.y + t.y);
    b = make_float2(a.x - t.x, a.y - t.y);
    a = na;
}
__device__ __forceinline__ void bf1(float2& a, float2& b) {  // tw = 1
    float2 na = make_float2(a.x + b.x, a.y + b.y);
    b = make_float2(a.x - b.x, a.y - b.y);
    a = na;
}
// Same butterfly on both rows, one twiddle load.
__device__ __forceinline__ void bf2(float2& a0, float2& b0,
                                    float2& a1, float2& b1, float2 tw) {
    bf(a0, b0, tw);
    bf(a1, b1, tw);
}

// Swap lane bit m with register bit rho on BOTH row arrays (16 SHFL).
__device__ __forceinline__ void swap_lr2(float2* Xa, float2* Xb, int lane,
                                         int m, int rho) {
    bool hi = (lane & m) != 0;
    #pragma unroll
    for (int n = 0; n < 8; n++) {
        if (n & rho) continue;
        int nh = n | rho;
        float2 sa = hi ? Xa[n] : Xa[nh];
        sa.x = __shfl_xor_sync(0xffffffffu, sa.x, m);
        sa.y = __shfl_xor_sync(0xffffffffu, sa.y, m);
        if (hi) Xa[n] = sa; else Xa[nh] = sa;
        float2 sb = hi ? Xb[n] : Xb[nh];
        sb.x = __shfl_xor_sync(0xffffffffu, sb.x, m);
        sb.y = __shfl_xor_sync(0xffffffffu, sb.y, m);
        if (hi) Xb[n] = sb; else Xb[nh] = sb;
    }
}

// Stages 1-8. Input: A layout (i = 8t + r). Output layout (folded into the
// exchange store): lanes l0..l4 = i0..i4, regs r0,r1,r2 = i6,i7,i5.
__device__ __forceinline__ void stages_1_8(float2* Xa, float2* Xb, int lane,
                                           const float2* TW) {
    // S1: bit 0, tw = 1
    bf1(Xa[0], Xa[1]); bf1(Xa[2], Xa[3]); bf1(Xa[4], Xa[5]); bf1(Xa[6], Xa[7]);
    bf1(Xb[0], Xb[1]); bf1(Xb[2], Xb[3]); bf1(Xb[4], Xb[5]); bf1(Xb[6], Xb[7]);
    // S2: bit 1, k = (r&1)<<10 ; tw(0) = 1
    {
        float2 tB = TW[padT(1 << 10)];
        bf1(Xa[0], Xa[2]); bf(Xa[1], Xa[3], tB);
        bf1(Xa[4], Xa[6]); bf(Xa[5], Xa[7], tB);
        bf1(Xb[0], Xb[2]); bf(Xb[1], Xb[3], tB);
        bf1(Xb[4], Xb[6]); bf(Xb[5], Xb[7], tB);
    }
    // S3: bit 2, k = (r&3)<<9 ; tw(0) = 1
    {
        float2 t1 = TW[padT(1 << 9)];
        float2 t2 = TW[padT(2 << 9)];
        float2 t3 = TW[padT(3 << 9)];
        bf1(Xa[0], Xa[4]); bf1(Xb[0], Xb[4]);
        bf2(Xa[1], Xa[5], Xb[1], Xb[5], t1);
        bf2(Xa[2], Xa[6], Xb[2], Xb[6], t2);
        bf2(Xa[3], Xa[7], Xb[3], Xb[7], t3);
    }
    // S4: swap(l0, reg bit0); work bit i3 at reg bit0. j = l0 + 2*i1 + 4*i2
    {
        swap_lr2(Xa, Xb, lane, 1, 1);
        int l0 = lane & 1;
        float2 t0 = TW[padT((l0 + 0) << 8)];
        float2 t1 = TW[padT((l0 + 2) << 8)];
        float2 t2 = TW[padT((l0 + 4) << 8)];
        float2 t3 = TW[padT((l0 + 6) << 8)];
        bf2(Xa[0], Xa[1], Xb[0], Xb[1], t0);
        bf2(Xa[2], Xa[3], Xb[2], Xb[3], t1);
        bf2(Xa[4], Xa[5], Xb[4], Xb[5], t2);
        bf2(Xa[6], Xa[7], Xb[6], Xb[7], t3);
    }
    // S5: swap(l1, reg bit1); j = (lane&3) + 4*i2(rb2) + 8*i3(rb0)
    {
        swap_lr2(Xa, Xb, lane, 2, 2);
        int l01 = lane & 3;
        float2 t0 = TW[padT((l01 + 0)  << 7)];
        float2 t1 = TW[padT((l01 + 8)  << 7)];
        float2 t2 = TW[padT((l01 + 4)  << 7)];
        float2 t3 = TW[padT((l01 + 12) << 7)];
        bf2(Xa[0], Xa[2], Xb[0], Xb[2], t0);
        bf2(Xa[1], Xa[3], Xb[1], Xb[3], t1);
        bf2(Xa[4], Xa[6], Xb[4], Xb[6], t2);
        bf2(Xa[5], Xa[7], Xb[5], Xb[7], t3);
    }
    // S6: swap(l2, reg bit2); j = (lane&7) + 8*i3(rb0) + 16*i4(rb1)
    {
        swap_lr2(Xa, Xb, lane, 4, 4);
        int l02 = lane & 7;
        float2 t0 = TW[padT((l02 + 0)  << 6)];
        float2 t1 = TW[padT((l02 + 8)  << 6)];
        float2 t2 = TW[padT((l02 + 16) << 6)];
        float2 t3 = TW[padT((l02 + 24) << 6)];
        bf2(Xa[0], Xa[4], Xb[0], Xb[4], t0);
        bf2(Xa[1], Xa[5], Xb[1], Xb[5], t1);
        bf2(Xa[2], Xa[6], Xb[2], Xb[6], t2);
        bf2(Xa[3], Xa[7], Xb[3], Xb[7], t3);
    }
    // S7: swap(l3, reg bit0); j = (lane&15) + 16*i4(rb1) + 32*i5(rb2)
    {
        swap_lr2(Xa, Xb, lane, 8, 1);
        int l03 = lane & 15;
        float2 t0 = TW[padT((l03 + 0)  << 5)];
        float2 t1 = TW[padT((l03 + 16) << 5)];
        float2 t2 = TW[padT((l03 + 32) << 5)];
        float2 t3 = TW[padT((l03 + 48) << 5)];
        bf2(Xa[0], Xa[1], Xb[0], Xb[1], t0);
        bf2(Xa[2], Xa[3], Xb[2], Xb[3], t1);
        bf2(Xa[4], Xa[5], Xb[4], Xb[5], t2);
        bf2(Xa[6], Xa[7], Xb[6], Xb[7], t3);
    }
    // S8: swap(l4, reg bit1); j = lane + 32*i5(rb2) + 64*i6(rb0)
    {
        swap_lr2(Xa, Xb, lane, 16, 2);
        float2 t0 = TW[padT((lane + 0)  << 4)];
        float2 t1 = TW[padT((lane + 64) << 4)];
        float2 t2 = TW[padT((lane + 32) << 4)];
        float2 t3 = TW[padT((lane + 96) << 4)];
        bf2(Xa[0], Xa[2], Xb[0], Xb[2], t0);
        bf2(Xa[1], Xa[3], Xb[1], Xb[3], t1);
        bf2(Xa[4], Xa[6], Xb[4], Xb[6], t2);
        bf2(Xa[5], Xa[7], Xb[5], Xb[7], t3);
    }
}

// True element index of register n after stages_1_8:
// i = lane + 32*c(n) + 256*w, with c(n) = i5 + 2*i6 + 4*i7
__device__ __forceinline__ int cmap(int n) {
    return ((n >> 2) & 1) + 2 * (n & 1) + 4 * ((n >> 1) & 1);
}

// Stages 9-12 on D-layout registers (i = tid9 | (r<<9)).
__device__ __forceinline__ void stages_9_12(float2* Xa, float2* Xb, int lane,
                                            int tid9, const float2* TW) {
    // S9: bit 8 = lane bit 0 ; k = (i & 255) << 3, uniform over r
    {
        bool up = (lane & 1) != 0;
        float2 tw = TW[padT((tid9 & 255) << 3)];
        #pragma unroll
        for (int r = 0; r < 8; r++) {
            float2 v = Xa[r];
            float2 p;
            p.x = __shfl_xor_sync(0xffffffffu, v.x, 1);
            p.y = __shfl_xor_sync(0xffffffffu, v.y, 1);
            if (up) { float2 tb = cmul(tw, v); Xa[r] = make_float2(p.x - tb.x, p.y - tb.y); }
            else    { float2 tb = cmul(tw, p); Xa[r] = make_float2(v.x + tb.x, v.y + tb.y); }
            float2 vb = Xb[r];
            float2 pb;
            pb.x = __shfl_xor_sync(0xffffffffu, vb.x, 1);
            pb.y = __shfl_xor_sync(0xffffffffu, vb.y, 1);
            if (up) { float2 tb = cmul(tw, vb); Xb[r] = make_float2(pb.x - tb.x, pb.y - tb.y); }
            else    { float2 tb = cmul(tw, pb); Xb[r] = make_float2(vb.x + tb.x, vb.y + tb.y); }
        }
    }
    // S10: bit 9 = r bit 0 ; k = tid9<<2
    {
        float2 tw = TW[padT(tid9 << 2)];
        bf2(Xa[0], Xa[1], Xb[0], Xb[1], tw);
        bf2(Xa[2], Xa[3], Xb[2], Xb[3], tw);
        bf2(Xa[4], Xa[5], Xb[4], Xb[5], tw);
        bf2(Xa[6], Xa[7], Xb[6], Xb[7], tw);
    }
    // S11: bit 10 = r bit 1 ; k = (tid9 | (r&1)<<9) << 1
    {
        float2 tA = TW[padT(tid9 << 1)];
        float2 tB = TW[padT((tid9 | 512) << 1)];
        bf2(Xa[0], Xa[2], Xb[0], Xb[2], tA);
        bf2(Xa[1], Xa[3], Xb[1], Xb[3], tB);
        bf2(Xa[4], Xa[6], Xb[4], Xb[6], tA);
        bf2(Xa[5], Xa[7], Xb[5], Xb[7], tB);
    }
    // S12: bit 11 = r bit 2 ; k = tid9 | (r&3)<<9
    {
        float2 t0 = TW[padT(tid9)];
        float2 t1 = TW[padT(tid9 | (1 << 9))];
        float2 t2 = TW[padT(tid9 | (2 << 9))];
        float2 t3 = TW[padT(tid9 | (3 << 9))];
        bf2(Xa[0], Xa[4], Xb[0], Xb[4], t0);
        bf2(Xa[1], Xa[5], Xb[1], Xb[5], t1);
        bf2(Xa[2], Xa[6], Xb[2], Xb[6], t2);
        bf2(Xa[3], Xa[7], Xb[3], Xb[7], t3);
    }
}

__global__ __launch_bounds__(NT, 2)
void mlp_fft_kernel(const float2* __restrict__ xin, float2* __restrict__ out) {
    extern __shared__ float2 sm[];
    float2* SA = sm;                 // DATA_F2  (row A)
    float2* SB = sm + DATA_F2;       // DATA_F2  (row B)
    float2* TW = sm + 2 * DATA_F2;   // TW_F2

    const int t    = threadIdx.x;
    const int lane = t & 31;
    const int w    = t >> 5;
    const int tid9 = (w << 4) | (lane >> 1) | ((lane & 1) << 8);
    const int rowA = 2 * blockIdx.x;

    float2 Xa[8], Xb[8];

    // --- Stage twiddles 1 (LDG.128, two STS.64 — padT breaks 16B alignment,
    //     so NO float4 shared store); load inputs (perm ^2048) ---
    #pragma unroll
    for (int u = 0; u < 2; u++) {
        int k = 2 * (t + u * NT);              // even k: padT(k+1) == padT(k)+1
        float4 v = ((const float4*)g_tw1)[t + u * NT];
        TW[padT(k)]     = make_float2(v.x, v.y);
        TW[padT(k) + 1] = make_float2(v.z, v.w);
    }
    {
        const float4* xa4 = (const float4*)(xin + (size_t)rowA * N_FFT);
        const float4* xb4 = xa4 + N_FFT / 2;
        #pragma unroll
        for (int c = 0; c < 4; c++) {
            float4 v = __ldg(&xa4[(4 * t + c) ^ 1024]);
            Xa[2 * c]     = make_float2(v.x, v.y);
            Xa[2 * c + 1] = make_float2(v.z, v.w);
            float4 vb = __ldg(&xb4[(4 * t + c) ^ 1024]);
            Xb[2 * c]     = make_float2(vb.x, vb.y);
            Xb[2 * c + 1] = make_float2(vb.z, vb.w);
        }
    }
    __syncthreads();   // TW1 ready

    // ================= Layer 1 =================
    stages_1_8(Xa, Xb, lane, TW);

    // Exchange (permuted A) -> D. Store each register at its TRUE index.
    #pragma unroll
    for (int n = 0; n < 8; n++) {
        int a = padD(lane + 32 * cmap(n) + 256 * w);
        SA[a] = Xa[n];
        SB[a] = Xb[n];
    }
    __syncthreads();
    #pragma unroll
    for (int r = 0; r < 8; r++) {
        int a = padD(tid9 | (r << 9));
        Xa[r] = SA[a];
        Xb[r] = SB[a];
    }

    stages_9_12(Xa, Xb, lane, tid9, TW);

    // ReLU + perm (^2048 flips r bit 2): register-local
    {
        float2 Ya[8], Yb[8];
        #pragma unroll
        for (int r = 0; r < 8; r++) {
            float2 va = Xa[r ^ 4];
            Ya[r] = make_float2(fmaxf(va.x, 0.f), fmaxf(va.y, 0.f));
            float2 vb = Xb[r ^ 4];
            Yb[r] = make_float2(fmaxf(vb.x, 0.f), fmaxf(vb.y, 0.f));
        }
        #pragma unroll
        for (int r = 0; r < 8; r++) { Xa[r] = Ya[r]; Xb[r] = Yb[r]; }
    }

    // Exchange D -> A, swap twiddle table to layer 2
    __syncthreads();   // prior readers done
    #pragma unroll
    for (int r = 0; r < 8; r++) {
        int a = padD(tid9 | (r << 9));
        SA[a] = Xa[r];
        SB[a] = Xb[r];
    }
    #pragma unroll
    for (int u = 0; u < 2; u++) {
        int k = 2 * (t + u * NT);
        float4 v = ((const float4*)g_tw2)[t + u * NT];
        TW[padT(k)]     = make_float2(v.x, v.y);
        TW[padT(k) + 1] = make_float2(v.z, v.w);
    }
    __syncthreads();
    #pragma unroll
    for (int r = 0; r < 8; r++) {
        int a = padD(8 * t + r);
        Xa[r] = SA[a];
        Xb[r] = SB[a];
    }

    // ================= Layer 2 =================
    stages_1_8(Xa, Xb, lane, TW);

    __syncthreads();   // prior A-layout readers done
    #pragma unroll
    for (int n = 0; n < 8; n++) {
        int a = padD(lane + 32 * cmap(n) + 256 * w);
        SA[a] = Xa[n];
        SB[a] = Xb[n];
    }
    __syncthreads();
    #pragma unroll
    for (int r = 0; r < 8; r++) {
        int a = padD(tid9 | (r << 9));
        Xa[r] = SA[a];
        Xb[r] = SB[a];
    }

    stages_9_12(Xa, Xb, lane, tid9, TW);

    // Output: first OUT_C complex of each row = D-octet regs r in {0,1}
    {
        float2* oa = out + (size_t)rowA * OUT_C;
        oa[tid9]                 = Xa[0];
        oa[tid9 + 512]           = Xa[1];
        oa[OUT_C + tid9]         = Xb[0];
        oa[OUT_C + tid9 + 512]   = Xb[1];
    }
}

extern "C" void kernel_launch(void* const* d_in, const int* in_sizes, int n_in,
                              void* d_out, int out_size) {
    const float* x  = (const float*)d_in[0];   // (4096, 8192) f32
    const float* w1 = (const float*)d_in[1];   // (2048,) f32
    const float* w2 = (const float*)d_in[2];   // (2048,) f32
    float* out = (float*)d_out;                // (4096, 2048) f32

    cudaFuncSetAttribute(mlp_fft_kernel,
                         cudaFuncAttributeMaxDynamicSharedMemorySize, SMEM_BYTES);

    twiddle_kernel<<<2, 1024>>>(w1, w2);
    mlp_fft_kernel<<<BATCH / 2, NT, SMEM_BYTES>>>((const float2*)x, (float2*)out);
}

// round 11
// speedup vs baseline: 4.2129x; 1.0152x over previous
#include <cuda_runtime.h>

// Fused FFT-butterfly MLP, register-resident butterflies, 2 rows per CTA.
// N=4096 complex/row, 12 radix-2 stages x 2 layers, ReLU+perm between.
// One CTA (512 thr) per PAIR of rows; each thread owns 8 complex per row.
// Rows A/B are packed as float4 in the smem exchanges (one STS/LDS for both).
// Layer 2 stages 11/12 compute only the surviving (i < 1024) outputs.

#define N_FFT    4096
#define HALF_N   2048
#define BATCH    4096
#define OUT_C    1024
#define NT       512

// Padded smem geometry
#define DATA_F4  4608              // float4 units: 4096 + 512 pad (i + (i>>3))
#define TW_F2    2176              // float2 units: 2048 + 128 pad (k + (k>>4))
#define SMEM_BYTES (DATA_F4 * (int)sizeof(float4) + TW_F2 * (int)sizeof(float2))  // 91136

__device__ __align__(16) float2 g_tw1[HALF_N];
__device__ __align__(16) float2 g_tw2[HALF_N];

__global__ void twiddle_kernel(const float* __restrict__ w1,
                               const float* __restrict__ w2) {
    int k = blockIdx.x * blockDim.x + threadIdx.x;
    if (k < HALF_N) {
        const float c = -6.283185307179586f / (float)N_FFT;
        float kk = (float)k;
        float s, co;
        sincosf(c * kk * w1[k], &s, &co);
        g_tw1[k] = make_float2(co, s);
        sincosf(c * kk * w2[k], &s, &co);
        g_tw2[k] = make_float2(co, s);
    }
}

__device__ __forceinline__ int padD(int i) { return i + (i >> 3); }
__device__ __forceinline__ int padT(int k) { return k + (k >> 4); }

__device__ __forceinline__ float2 cmul(float2 a, float2 b) {
    return make_float2(a.x * b.x - a.y * b.y, a.x * b.y + a.y * b.x);
}

// butterfly: a' = a + tw*b ; b' = a - tw*b
__device__ __forceinline__ void bf(float2& a, float2& b, float2 tw) {
    float2 t = cmul(tw, b);
    float2 na = make_float2(a.x + t.x, a.y + t.y);
    b = make_float2(a.x - t.x, a.y - t.y);
    a = na;
}
__device__ __forceinline__ void bf1(float2& a, float2& b) {  // tw = 1
    float2 na = make_float2(a.x + b.x, a.y + b.y);
    b = make_float2(a.x - b.x, a.y - b.y);
    a = na;
}
__device__ __forceinline__ void bf2(float2& a0, float2& b0,
                                    float2& a1, float2& b1, float2 tw) {
    bf(a0, b0, tw);
    bf(a1, b1, tw);
}
// half-butterfly: keep only a' = a + tw*b (discard the '-' output)
__device__ __forceinline__ void hbf(float2& a, const float2 b, float2 tw) {
    float2 t = cmul(tw, b);
    a = make_float2(a.x + t.x, a.y + t.y);
}

// Swap lane bit m with register bit rho on BOTH row arrays (16 SHFL).
__device__ __forceinline__ void swap_lr2(float2* Xa, float2* Xb, int lane,
                                         int m, int rho) {
    bool hi = (lane & m) != 0;
    #pragma unroll
    for (int n = 0; n < 8; n++) {
        if (n & rho) continue;
        int nh = n | rho;
        float2 sa = hi ? Xa[n] : Xa[nh];
        sa.x = __shfl_xor_sync(0xffffffffu, sa.x, m);
        sa.y = __shfl_xor_sync(0xffffffffu, sa.y, m);
        if (hi) Xa[n] = sa; else Xa[nh] = sa;
        float2 sb = hi ? Xb[n] : Xb[nh];
        sb.x = __shfl_xor_sync(0xffffffffu, sb.x, m);
        sb.y = __shfl_xor_sync(0xffffffffu, sb.y, m);
        if (hi) Xb[n] = sb; else Xb[nh] = sb;
    }
}

// Stages 1-8. Input: A layout (i = 8t + r). Output layout (folded into the
// exchange store): lanes l0..l4 = i0..i4, regs r0,r1,r2 = i6,i7,i5.
__device__ __forceinline__ void stages_1_8(float2* Xa, float2* Xb, int lane,
                                           const float2* TW) {
    // S1: bit 0, tw = 1
    bf1(Xa[0], Xa[1]); bf1(Xa[2], Xa[3]); bf1(Xa[4], Xa[5]); bf1(Xa[6], Xa[7]);
    bf1(Xb[0], Xb[1]); bf1(Xb[2], Xb[3]); bf1(Xb[4], Xb[5]); bf1(Xb[6], Xb[7]);
    // S2: bit 1, k = (r&1)<<10 ; tw(0) = 1
    {
        float2 tB = TW[padT(1 << 10)];
        bf1(Xa[0], Xa[2]); bf(Xa[1], Xa[3], tB);
        bf1(Xa[4], Xa[6]); bf(Xa[5], Xa[7], tB);
        bf1(Xb[0], Xb[2]); bf(Xb[1], Xb[3], tB);
        bf1(Xb[4], Xb[6]); bf(Xb[5], Xb[7], tB);
    }
    // S3: bit 2, k = (r&3)<<9 ; tw(0) = 1
    {
        float2 t1 = TW[padT(1 << 9)];
        float2 t2 = TW[padT(2 << 9)];
        float2 t3 = TW[padT(3 << 9)];
        bf1(Xa[0], Xa[4]); bf1(Xb[0], Xb[4]);
        bf2(Xa[1], Xa[5], Xb[1], Xb[5], t1);
        bf2(Xa[2], Xa[6], Xb[2], Xb[6], t2);
        bf2(Xa[3], Xa[7], Xb[3], Xb[7], t3);
    }
    // S4: swap(l0, reg bit0); work bit i3 at reg bit0. j = l0 + 2*i1 + 4*i2
    {
        swap_lr2(Xa, Xb, lane, 1, 1);
        int l0 = lane & 1;
        float2 t0 = TW[padT((l0 + 0) << 8)];
        float2 t1 = TW[padT((l0 + 2) << 8)];
        float2 t2 = TW[padT((l0 + 4) << 8)];
        float2 t3 = TW[padT((l0 + 6) << 8)];
        bf2(Xa[0], Xa[1], Xb[0], Xb[1], t0);
        bf2(Xa[2], Xa[3], Xb[2], Xb[3], t1);
        bf2(Xa[4], Xa[5], Xb[4], Xb[5], t2);
        bf2(Xa[6], Xa[7], Xb[6], Xb[7], t3);
    }
    // S5: swap(l1, reg bit1); j = (lane&3) + 4*i2(rb2) + 8*i3(rb0)
    {
        swap_lr2(Xa, Xb, lane, 2, 2);
        int l01 = lane & 3;
        float2 t0 = TW[padT((l01 + 0)  << 7)];
        float2 t1 = TW[padT((l01 + 8)  << 7)];
        float2 t2 = TW[padT((l01 + 4)  << 7)];
        float2 t3 = TW[padT((l01 + 12) << 7)];
        bf2(Xa[0], Xa[2], Xb[0], Xb[2], t0);
        bf2(Xa[1], Xa[3], Xb[1], Xb[3], t1);
        bf2(Xa[4], Xa[6], Xb[4], Xb[6], t2);
        bf2(Xa[5], Xa[7], Xb[5], Xb[7], t3);
    }
    // S6: swap(l2, reg bit2); j = (lane&7) + 8*i3(rb0) + 16*i4(rb1)
    {
        swap_lr2(Xa, Xb, lane, 4, 4);
        int l02 = lane & 7;
        float2 t0 = TW[padT((l02 + 0)  << 6)];
        float2 t1 = TW[padT((l02 + 8)  << 6)];
        float2 t2 = TW[padT((l02 + 16) << 6)];
        float2 t3 = TW[padT((l02 + 24) << 6)];
        bf2(Xa[0], Xa[4], Xb[0], Xb[4], t0);
        bf2(Xa[1], Xa[5], Xb[1], Xb[5], t1);
        bf2(Xa[2], Xa[6], Xb[2], Xb[6], t2);
        bf2(Xa[3], Xa[7], Xb[3], Xb[7], t3);
    }
    // S7: swap(l3, reg bit0); j = (lane&15) + 16*i4(rb1) + 32*i5(rb2)
    {
        swap_lr2(Xa, Xb, lane, 8, 1);
        int l03 = lane & 15;
        float2 t0 = TW[padT((l03 + 0)  << 5)];
        float2 t1 = TW[padT((l03 + 16) << 5)];
        float2 t2 = TW[padT((l03 + 32) << 5)];
        float2 t3 = TW[padT((l03 + 48) << 5)];
        bf2(Xa[0], Xa[1], Xb[0], Xb[1], t0);
        bf2(Xa[2], Xa[3], Xb[2], Xb[3], t1);
        bf2(Xa[4], Xa[5], Xb[4], Xb[5], t2);
        bf2(Xa[6], Xa[7], Xb[6], Xb[7], t3);
    }
    // S8: swap(l4, reg bit1); j = lane + 32*i5(rb2) + 64*i6(rb0)
    {
        swap_lr2(Xa, Xb, lane, 16, 2);
        float2 t0 = TW[padT((lane + 0)  << 4)];
        float2 t1 = TW[padT((lane + 64) << 4)];
        float2 t2 = TW[padT((lane + 32) << 4)];
        float2 t3 = TW[padT((lane + 96) << 4)];
        bf2(Xa[0], Xa[2], Xb[0], Xb[2], t0);
        bf2(Xa[1], Xa[3], Xb[1], Xb[3], t1);
        bf2(Xa[4], Xa[6], Xb[4], Xb[6], t2);
        bf2(Xa[5], Xa[7], Xb[5], Xb[7], t3);
    }
}

// True element index of register n after stages_1_8:
// i = lane + 32*c(n) + 256*w, with c(n) = i5 + 2*i6 + 4*i7
__device__ __forceinline__ int cmap(int n) {
    return ((n >> 2) & 1) + 2 * (n & 1) + 4 * ((n >> 1) & 1);
}

// Stages 9-10 on D-layout registers (i = tid9 | (r<<9)), shared by both layers.
__device__ __forceinline__ void stages_9_10(float2* Xa, float2* Xb, int lane,
                                            int tid9, const float2* TW) {
    // S9: bit 8 = lane bit 0 ; k = (i & 255) << 3, uniform over r
    {
        bool up = (lane & 1) != 0;
        float2 tw = TW[padT((tid9 & 255) << 3)];
        #pragma unroll
        for (int r = 0; r < 8; r++) {
            float2 v = Xa[r];
            float2 p;
            p.x = __shfl_xor_sync(0xffffffffu, v.x, 1);
            p.y = __shfl_xor_sync(0xffffffffu, v.y, 1);
            if (up) { float2 tb = cmul(tw, v); Xa[r] = make_float2(p.x - tb.x, p.y - tb.y); }
            else    { float2 tb = cmul(tw, p); Xa[r] = make_float2(v.x + tb.x, v.y + tb.y); }
            float2 vb = Xb[r];
            float2 pb;
            pb.x = __shfl_xor_sync(0xffffffffu, vb.x, 1);
            pb.y = __shfl_xor_sync(0xffffffffu, vb.y, 1);
            if (up) { float2 tb = cmul(tw, vb); Xb[r] = make_float2(pb.x - tb.x, pb.y - tb.y); }
            else    { float2 tb = cmul(tw, pb); Xb[r] = make_float2(vb.x + tb.x, vb.y + tb.y); }
        }
    }
    // S10: bit 9 = r bit 0 ; k = tid9<<2
    {
        float2 tw = TW[padT(tid9 << 2)];
        bf2(Xa[0], Xa[1], Xb[0], Xb[1], tw);
        bf2(Xa[2], Xa[3], Xb[2], Xb[3], tw);
        bf2(Xa[4], Xa[5], Xb[4], Xb[5], tw);
        bf2(Xa[6], Xa[7], Xb[6], Xb[7], tw);
    }
}

// Full stages 11-12 (layer 1: all outputs needed).
__device__ __forceinline__ void stages_11_12_full(float2* Xa, float2* Xb,
                                                  int tid9, const float2* TW) {
    // S11: bit 10 = r bit 1 ; k = (tid9 | (r&1)<<9) << 1
    {
        float2 tA = TW[padT(tid9 << 1)];
        float2 tB = TW[padT((tid9 | 512) << 1)];
        bf2(Xa[0], Xa[2], Xb[0], Xb[2], tA);
        bf2(Xa[1], Xa[3], Xb[1], Xb[3], tB);
        bf2(Xa[4], Xa[6], Xb[4], Xb[6], tA);
        bf2(Xa[5], Xa[7], Xb[5], Xb[7], tB);
    }
    // S12: bit 11 = r bit 2 ; k = tid9 | (r&3)<<9
    {
        float2 t0 = TW[padT(tid9)];
        float2 t1 = TW[padT(tid9 | (1 << 9))];
        float2 t2 = TW[padT(tid9 | (2 << 9))];
        float2 t3 = TW[padT(tid9 | (3 << 9))];
        bf2(Xa[0], Xa[4], Xb[0], Xb[4], t0);
        bf2(Xa[1], Xa[5], Xb[1], Xb[5], t1);
        bf2(Xa[2], Xa[6], Xb[2], Xb[6], t2);
        bf2(Xa[3], Xa[7], Xb[3], Xb[7], t3);
    }
}

// Truncated stages 11-12 (layer 2): only outputs with i < 1024 (r in {0,1})
// survive. S11 needs only the '+' side for r in {0,1,4,5}; S12 only pairs
// (0,4) and (1,5), '+' side.
__device__ __forceinline__ void stages_11_12_trunc(float2* Xa, float2* Xb,
                                                   int tid9, const float2* TW) {
    {
        float2 tA = TW[padT(tid9 << 1)];
        float2 tB = TW[padT((tid9 | 512) << 1)];
        hbf(Xa[0], Xa[2], tA); hbf(Xb[0], Xb[2], tA);
        hbf(Xa[1], Xa[3], tB); hbf(Xb[1], Xb[3], tB);
        hbf(Xa[4], Xa[6], tA); hbf(Xb[4], Xb[6], tA);
        hbf(Xa[5], Xa[7], tB); hbf(Xb[5], Xb[7], tB);
    }
    {
        float2 t0 = TW[padT(tid9)];
        float2 t1 = TW[padT(tid9 | (1 << 9))];
        hbf(Xa[0], Xa[4], t0); hbf(Xb[0], Xb[4], t0);
        hbf(Xa[1], Xa[5], t1); hbf(Xb[1], Xb[5], t1);
    }
}

__global__ __launch_bounds__(NT, 2)
void mlp_fft_kernel(const float2* __restrict__ xin, float2* __restrict__ out) {
    extern __shared__ float4 sm4[];
    float4* SD = sm4;                          // DATA_F4 float4 (rows A+B packed)
    float2* TW = (float2*)(sm4 + DATA_F4);     // TW_F2 float2

    const int t    = threadIdx.x;
    const int lane = t & 31;
    const int w    = t >> 5;
    const int tid9 = (w << 4) | (lane >> 1) | ((lane & 1) << 8);
    const int rowA = 2 * blockIdx.x;

    float2 Xa[8], Xb[8];

    // --- Stage twiddles 1 (LDG.128 -> two STS.64; padT breaks 16B alignment
    //     in float2 units so no vector shared store); load inputs (perm ^2048) ---
    #pragma unroll
    for (int u = 0; u < 2; u++) {
        int k = 2 * (t + u * NT);              // even k: padT(k+1) == padT(k)+1
        float4 v = ((const float4*)g_tw1)[t + u * NT];
        TW[padT(k)]     = make_float2(v.x, v.y);
        TW[padT(k) + 1] = make_float2(v.z, v.w);
    }
    {
        const float4* xa4 = (const float4*)(xin + (size_t)rowA * N_FFT);
        const float4* xb4 = xa4 + N_FFT / 2;
        #pragma unroll
        for (int c = 0; c < 4; c++) {
            float4 v = __ldg(&xa4[(4 * t + c) ^ 1024]);
            Xa[2 * c]     = make_float2(v.x, v.y);
            Xa[2 * c + 1] = make_float2(v.z, v.w);
            float4 vb = __ldg(&xb4[(4 * t + c) ^ 1024]);
            Xb[2 * c]     = make_float2(vb.x, vb.y);
            Xb[2 * c + 1] = make_float2(vb.z, vb.w);
        }
    }
    __syncthreads();   // TW1 ready

    // ================= Layer 1 =================
    stages_1_8(Xa, Xb, lane, TW);

    // Exchange (permuted A) -> D, rows packed in one float4.
    #pragma unroll
    for (int n = 0; n < 8; n++)
        SD[padD(lane + 32 * cmap(n) + 256 * w)] =
            make_float4(Xa[n].x, Xa[n].y, Xb[n].x, Xb[n].y);
    __syncthreads();
    #pragma unroll
    for (int r = 0; r < 8; r++) {
        float4 v = SD[padD(tid9 | (r << 9))];
        Xa[r] = make_float2(v.x, v.y);
        Xb[r] = make_float2(v.z, v.w);
    }

    stages_9_10(Xa, Xb, lane, tid9, TW);
    stages_11_12_full(Xa, Xb, tid9, TW);

    // ReLU + perm (^2048 flips r bit 2): register-local
    {
        float2 Ya[8], Yb[8];
        #pragma unroll
        for (int r = 0; r < 8; r++) {
            float2 va = Xa[r ^ 4];
            Ya[r] = make_float2(fmaxf(va.x, 0.f), fmaxf(va.y, 0.f));
            float2 vb = Xb[r ^ 4];
            Yb[r] = make_float2(fmaxf(vb.x, 0.f), fmaxf(vb.y, 0.f));
        }
        #pragma unroll
        for (int r = 0; r < 8; r++) { Xa[r] = Ya[r]; Xb[r] = Yb[r]; }
    }

    // Exchange D -> A, swap twiddle table to layer 2
    __syncthreads();   // prior readers done
    #pragma unroll
    for (int r = 0; r < 8; r++)
        SD[padD(tid9 | (r << 9))] =
            make_float4(Xa[r].x, Xa[r].y, Xb[r].x, Xb[r].y);
    #pragma unroll
    for (int u = 0; u < 2; u++) {
        int k = 2 * (t + u * NT);
        float4 v = ((const float4*)g_tw2)[t + u * NT];
        TW[padT(k)]     = make_float2(v.x, v.y);
        TW[padT(k) + 1] = make_float2(v.z, v.w);
    }
    __syncthreads();
    #pragma unroll
    for (int r = 0; r < 8; r++) {
        float4 v = SD[padD(8 * t + r)];
        Xa[r] = make_float2(v.x, v.y);
        Xb[r] = make_float2(v.z, v.w);
    }

    // ================= Layer 2 =================
    stages_1_8(Xa, Xb, lane, TW);

    __syncthreads();   // prior A-layout readers done
    #pragma unroll
    for (int n = 0; n < 8; n++)
        SD[padD(lane + 32 * cmap(n) + 256 * w)] =
            make_float4(Xa[n].x, Xa[n].y, Xb[n].x, Xb[n].y);
    __syncthreads();
    #pragma unroll
    for (int r = 0; r < 8; r++) {
        float4 v = SD[padD(tid9 | (r << 9))];
        Xa[r] = make_float2(v.x, v.y);
        Xb[r] = make_float2(v.z, v.w);
    }

    stages_9_10(Xa, Xb, lane, tid9, TW);
    stages_11_12_trunc(Xa, Xb, tid9, TW);

    // Output: first OUT_C complex of each row = D-octet regs r in {0,1}
    {
        float2* oa = out + (size_t)rowA * OUT_C;
        oa[tid9]                 = Xa[0];
        oa[tid9 + 512]           = Xa[1];
        oa[OUT_C + tid9]         = Xb[0];
        oa[OUT_C + tid9 + 512]   = Xb[1];
    }
}

extern "C" void kernel_launch(void* const* d_in, const int* in_sizes, int n_in,
                              void* d_out, int out_size) {
    const float* x  = (const float*)d_in[0];   // (4096, 8192) f32
    const float* w1 = (const float*)d_in[1];   // (2048,) f32
    const float* w2 = (const float*)d_in[2];   // (2048,) f32
    float* out = (float*)d_out;                // (4096, 2048) f32

    cudaFuncSetAttribute(mlp_fft_kernel,
                         cudaFuncAttributeMaxDynamicSharedMemorySize, SMEM_BYTES);

    twiddle_kernel<<<2, 1024>>>(w1, w2);
    mlp_fft_kernel<<<BATCH / 2, NT, SMEM_BYTES>>>((const float2*)x, (float2*)out);
}

// round 12
// speedup vs baseline: 4.2552x; 1.0100x over previous
#include <cuda_runtime.h>

// Fused FFT-butterfly MLP. 2 rows per CTA, register-resident butterflies,
// and SIMD-across-rows arithmetic: rows A/B live in packed f32x2 registers
// (XP = (Ax,Bx), YP = (Ay,By)), so each both-rows butterfly is 9 packed ops
// (mul/add/fma .f32x2) instead of 16 scalar FFMA-class ops.
// Stages 1-3: register bits. Stages 4-8: lane<->reg bit swaps + local
// butterflies. Stage 9 via broadcast-twiddle shuffle; 10-12 register bits.
// Layer 2 stages 11/12 compute only surviving (i < 1024) outputs.

#define N_FFT    4096
#define HALF_N   2048
#define BATCH    4096
#define OUT_C    1024
#define NT       512

#define DATA_F4  4608              // ulonglong2 units: 4096 + 512 pad (i + (i>>3))
#define TW_F2    2176              // float2 units: 2048 + 128 pad (k + (k>>4))
#define SMEM_BYTES (DATA_F4 * (int)sizeof(ulonglong2) + TW_F2 * (int)sizeof(float2))

typedef unsigned long long ull;

__device__ __align__(16) float2 g_tw1[HALF_N];
__device__ __align__(16) float2 g_tw2[HALF_N];

__global__ void twiddle_kernel(const float* __restrict__ w1,
                               const float* __restrict__ w2) {
    int k = blockIdx.x * blockDim.x + threadIdx.x;
    if (k < HALF_N) {
        const float c = -6.283185307179586f / (float)N_FFT;
        float kk = (float)k;
        float s, co;
        sincosf(c * kk * w1[k], &s, &co);
        g_tw1[k] = make_float2(co, s);
        sincosf(c * kk * w2[k], &s, &co);
        g_tw2[k] = make_float2(co, s);
    }
}

__device__ __forceinline__ int padD(int i) { return i + (i >> 3); }
__device__ __forceinline__ int padT(int k) { return k + (k >> 4); }

// ---- packed f32x2 primitives ----
#define F2MUL(d, a, b)    asm("mul.rn.f32x2 %0, %1, %2;"     : "=l"(d) : "l"(a), "l"(b))
#define F2ADD(d, a, b)    asm("add.rn.f32x2 %0, %1, %2;"     : "=l"(d) : "l"(a), "l"(b))
#define F2FMA(d, a, b, c) asm("fma.rn.f32x2 %0, %1, %2, %3;" : "=l"(d) : "l"(a), "l"(b), "l"(c))

__device__ __forceinline__ ull pack2(float lo, float hi) {
    ull r; asm("mov.b64 %0, {%1, %2};" : "=l"(r) : "f"(lo), "f"(hi)); return r;
}
__device__ __forceinline__ float lo32(ull u) { return __uint_as_float((unsigned)u); }
__device__ __forceinline__ float hi32(ull u) { return __uint_as_float((unsigned)(u >> 32)); }

struct PC { ull cc, ss; };   // twiddle broadcast: (c,c), (s,s)
__device__ __forceinline__ PC ldtw(const float2* __restrict__ TW, int kpad) {
    float2 t = TW[kpad];
    PC p; p.cc = pack2(t.x, t.x); p.ss = pack2(t.y, t.y); return p;
}

// packed butterfly on both rows: a' = a + w*b ; b' = a - w*b   (9 packed ops)
__device__ __forceinline__ void bfp(ull& aX, ull& aY, ull& bX, ull& bY,
                                    const PC w, const ull N1) {
    ull q, p, tX, r2, tY, nbX, nbY;
    F2MUL(q, w.cc, bX); F2MUL(p, w.ss, bY); F2FMA(tX, N1, p, q);   // t.x = c*bx - s*by
    F2MUL(r2, w.cc, bY); F2FMA(tY, w.ss, bX, r2);                  // t.y = c*by + s*bx
    F2FMA(nbX, N1, tX, aX); F2FMA(nbY, N1, tY, aY);                // b' = a - t
    F2ADD(aX, aX, tX); F2ADD(aY, aY, tY);                          // a' = a + t
    bX = nbX; bY = nbY;
}
// tw = 1 butterfly (4 packed ops)
__device__ __forceinline__ void bf1p(ull& aX, ull& aY, ull& bX, ull& bY,
                                     const ull N1) {
    ull nbX, nbY;
    F2FMA(nbX, N1, bX, aX); F2FMA(nbY, N1, bY, aY);
    F2ADD(aX, aX, bX); F2ADD(aY, aY, bY);
    bX = nbX; bY = nbY;
}
// half-butterfly: a' = a + w*b only (5 packed ops)
__device__ __forceinline__ void hbfp(ull& aX, ull& aY, const ull bX, const ull bY,
                                     const PC w, const ull N1) {
    ull t1, p, t2;
    F2FMA(t1, w.cc, bX, aX); F2MUL(p, w.ss, bY); F2FMA(aX, N1, p, t1);
    F2FMA(t2, w.cc, bY, aY); F2FMA(aY, w.ss, bX, t2);
}

// Swap lane bit m with register bit rho (both packed arrays; 16 SHFL.b32).
__device__ __forceinline__ void swap_lrp(ull* XP, ull* YP, int lane, int m, int rho) {
    bool hi = (lane & m) != 0;
    #pragma unroll
    for (int n = 0; n < 8; n++) {
        if (n & rho) continue;
        int nh = n | rho;
        ull sx = hi ? XP[n] : XP[nh];
        sx = __shfl_xor_sync(0xffffffffu, sx, m);
        if (hi) XP[n] = sx; else XP[nh] = sx;
        ull sy = hi ? YP[n] : YP[nh];
        sy = __shfl_xor_sync(0xffffffffu, sy, m);
        if (hi) YP[n] = sy; else YP[nh] = sy;
    }
}

// Stages 1-8. Input: A layout (i = 8t + r). Output layout (folded into the
// exchange store): lanes l0..l4 = i0..i4, regs r0,r1,r2 = i6,i7,i5.
__device__ __forceinline__ void stages_1_8(ull* XP, ull* YP, int lane,
                                           const float2* __restrict__ TW,
                                           const ull N1) {
    // S1: bit 0, tw = 1
    bf1p(XP[0],YP[0],XP[1],YP[1],N1); bf1p(XP[2],YP[2],XP[3],YP[3],N1);
    bf1p(XP[4],YP[4],XP[5],YP[5],N1); bf1p(XP[6],YP[6],XP[7],YP[7],N1);
    // S2: bit 1, k = (r&1)<<10 ; tw(0) = 1
    {
        PC tB = ldtw(TW, padT(1 << 10));
        bf1p(XP[0],YP[0],XP[2],YP[2],N1); bfp(XP[1],YP[1],XP[3],YP[3],tB,N1);
        bf1p(XP[4],YP[4],XP[6],YP[6],N1); bfp(XP[5],YP[5],XP[7],YP[7],tB,N1);
    }
    // S3: bit 2, k = (r&3)<<9 ; tw(0) = 1
    {
        PC t1 = ldtw(TW, padT(1 << 9));
        PC t2 = ldtw(TW, padT(2 << 9));
        PC t3 = ldtw(TW, padT(3 << 9));
        bf1p(XP[0],YP[0],XP[4],YP[4],N1);
        bfp(XP[1],YP[1],XP[5],YP[5],t1,N1);
        bfp(XP[2],YP[2],XP[6],YP[6],t2,N1);
        bfp(XP[3],YP[3],XP[7],YP[7],t3,N1);
    }
    // S4: swap(l0, rb0); j = l0 + 2*i1 + 4*i2
    {
        swap_lrp(XP, YP, lane, 1, 1);
        int l0 = lane & 1;
        PC t0 = ldtw(TW, padT((l0 + 0) << 8));
        PC t1 = ldtw(TW, padT((l0 + 2) << 8));
        PC t2 = ldtw(TW, padT((l0 + 4) << 8));
        PC t3 = ldtw(TW, padT((l0 + 6) << 8));
        bfp(XP[0],YP[0],XP[1],YP[1],t0,N1);
        bfp(XP[2],YP[2],XP[3],YP[3],t1,N1);
        bfp(XP[4],YP[4],XP[5],YP[5],t2,N1);
        bfp(XP[6],YP[6],XP[7],YP[7],t3,N1);
    }
    // S5: swap(l1, rb1); j = (lane&3) + 4*i2(rb2) + 8*i3(rb0)
    {
        swap_lrp(XP, YP, lane, 2, 2);
        int l01 = lane & 3;
        PC t0 = ldtw(TW, padT((l01 + 0)  << 7));
        PC t1 = ldtw(TW, padT((l01 + 8)  << 7));
        PC t2 = ldtw(TW, padT((l01 + 4)  << 7));
        PC t3 = ldtw(TW, padT((l01 + 12) << 7));
        bfp(XP[0],YP[0],XP[2],YP[2],t0,N1);
        bfp(XP[1],YP[1],XP[3],YP[3],t1,N1);
        bfp(XP[4],YP[4],XP[6],YP[6],t2,N1);
        bfp(XP[5],YP[5],XP[7],YP[7],t3,N1);
    }
    // S6: swap(l2, rb2); j = (lane&7) + 8*i3(rb0) + 16*i4(rb1)
    {
        swap_lrp(XP, YP, lane, 4, 4);
        int l02 = lane & 7;
        PC t0 = ldtw(TW, padT((l02 + 0)  << 6));
        PC t1 = ldtw(TW, padT((l02 + 8)  << 6));
        PC t2 = ldtw(TW, padT((l02 + 16) << 6));
        PC t3 = ldtw(TW, padT((l02 + 24) << 6));
        bfp(XP[0],YP[0],XP[4],YP[4],t0,N1);
        bfp(XP[1],YP[1],XP[5],YP[5],t1,N1);
        bfp(XP[2],YP[2],XP[6],YP[6],t2,N1);
        bfp(XP[3],YP[3],XP[7],YP[7],t3,N1);
    }
    // S7: swap(l3, rb0); j = (lane&15) + 16*i4(rb1) + 32*i5(rb2)
    {
        swap_lrp(XP, YP, lane, 8, 1);
        int l03 = lane & 15;
        PC t0 = ldtw(TW, padT((l03 + 0)  << 5));
        PC t1 = ldtw(TW, padT((l03 + 16) << 5));
        PC t2 = ldtw(TW, padT((l03 + 32) << 5));
        PC t3 = ldtw(TW, padT((l03 + 48) << 5));
        bfp(XP[0],YP[0],XP[1],YP[1],t0,N1);
        bfp(XP[2],YP[2],XP[3],YP[3],t1,N1);
        bfp(XP[4],YP[4],XP[5],YP[5],t2,N1);
        bfp(XP[6],YP[6],XP[7],YP[7],t3,N1);
    }
    // S8: swap(l4, rb1); j = lane + 32*i5(rb2) + 64*i6(rb0)
    {
        swap_lrp(XP, YP, lane, 16, 2);
        PC t0 = ldtw(TW, padT((lane + 0)  << 4));
        PC t1 = ldtw(TW, padT((lane + 64) << 4));
        PC t2 = ldtw(TW, padT((lane + 32) << 4));
        PC t3 = ldtw(TW, padT((lane + 96) << 4));
        bfp(XP[0],YP[0],XP[2],YP[2],t0,N1);
        bfp(XP[1],YP[1],XP[3],YP[3],t1,N1);
        bfp(XP[4],YP[4],XP[6],YP[6],t2,N1);
        bfp(XP[5],YP[5],XP[7],YP[7],t3,N1);
    }
}

// True element index of register n after stages_1_8:
// i = lane + 32*c(n) + 256*w, with c(n) = i5 + 2*i6 + 4*i7
__device__ __forceinline__ int cmap(int n) {
    return ((n >> 2) & 1) + 2 * (n & 1) + 4 * ((n >> 1) & 1);
}

// Stages 9-10 on D-layout registers (i = tid9 | (r<<9)).
__device__ __forceinline__ void stages_9_10(ull* XP, ull* YP, int lane, int tid9,
                                            const float2* __restrict__ TW,
                                            const ull N1) {
    // S9: bit 8 = lane bit 0 ; k = (i & 255) << 3, uniform over r
    {
        bool up = (lane & 1) != 0;
        PC w = ldtw(TW, padT((tid9 & 255) << 3));
        #pragma unroll
        for (int r = 0; r < 8; r++) {
            ull vX = XP[r], vY = YP[r];
            ull pX = __shfl_xor_sync(0xffffffffu, vX, 1);
            ull pY = __shfl_xor_sync(0xffffffffu, vY, 1);
            ull q, p2, tX, r2, tY;
            if (up) {   // own = b, partner = a : result = a - w*b
                F2MUL(q, w.cc, vX); F2MUL(p2, w.ss, vY); F2FMA(tX, N1, p2, q);
                F2MUL(r2, w.cc, vY); F2FMA(tY, w.ss, vX, r2);
                F2FMA(XP[r], N1, tX, pX); F2FMA(YP[r], N1, tY, pY);
            } else {    // own = a, partner = b : result = a + w*b
                F2MUL(q, w.cc, pX); F2MUL(p2, w.ss, pY); F2FMA(tX, N1, p2, q);
                F2MUL(r2, w.cc, pY); F2FMA(tY, w.ss, pX, r2);
                F2ADD(XP[r], vX, tX); F2ADD(YP[r], vY, tY);
            }
        }
    }
    // S10: bit 9 = r bit 0 ; k = tid9<<2
    {
        PC w = ldtw(TW, padT(tid9 << 2));
        bfp(XP[0],YP[0],XP[1],YP[1],w,N1);
        bfp(XP[2],YP[2],XP[3],YP[3],w,N1);
        bfp(XP[4],YP[4],XP[5],YP[5],w,N1);
        bfp(XP[6],YP[6],XP[7],YP[7],w,N1);
    }
}

// Full stages 11-12 (layer 1).
__device__ __forceinline__ void stages_11_12_full(ull* XP, ull* YP, int tid9,
                                                  const float2* __restrict__ TW,
                                                  const ull N1) {
    {
        PC tA = ldtw(TW, padT(tid9 << 1));
        PC tB = ldtw(TW, padT((tid9 | 512) << 1));
        bfp(XP[0],YP[0],XP[2],YP[2],tA,N1);
        bfp(XP[1],YP[1],XP[3],YP[3],tB,N1);
        bfp(XP[4],YP[4],XP[6],YP[6],tA,N1);
        bfp(XP[5],YP[5],XP[7],YP[7],tB,N1);
    }
    {
        PC t0 = ldtw(TW, padT(tid9));
        PC t1 = ldtw(TW, padT(tid9 | (1 << 9)));
        PC t2 = ldtw(TW, padT(tid9 | (2 << 9)));
        PC t3 = ldtw(TW, padT(tid9 | (3 << 9)));
        bfp(XP[0],YP[0],XP[4],YP[4],t0,N1);
        bfp(XP[1],YP[1],XP[5],YP[5],t1,N1);
        bfp(XP[2],YP[2],XP[6],YP[6],t2,N1);
        bfp(XP[3],YP[3],XP[7],YP[7],t3,N1);
    }
}

// Truncated stages 11-12 (layer 2): only i < 1024 outputs (r in {0,1}).
__device__ __forceinline__ void stages_11_12_trunc(ull* XP, ull* YP, int tid9,
                                                   const float2* __restrict__ TW,
                                                   const ull N1) {
    {
        PC tA = ldtw(TW, padT(tid9 << 1));
        PC tB = ldtw(TW, padT((tid9 | 512) << 1));
        hbfp(XP[0],YP[0],XP[2],YP[2],tA,N1);
        hbfp(XP[1],YP[1],XP[3],YP[3],tB,N1);
        hbfp(XP[4],YP[4],XP[6],YP[6],tA,N1);
        hbfp(XP[5],YP[5],XP[7],YP[7],tB,N1);
    }
    {
        PC t0 = ldtw(TW, padT(tid9));
        PC t1 = ldtw(TW, padT(tid9 | (1 << 9)));
        hbfp(XP[0],YP[0],XP[4],YP[4],t0,N1);
        hbfp(XP[1],YP[1],XP[5],YP[5],t1,N1);
    }
}

__device__ __forceinline__ ull relup(ull u) {
    return pack2(fmaxf(lo32(u), 0.f), fmaxf(hi32(u), 0.f));
}

__global__ __launch_bounds__(NT, 2)
void mlp_fft_kernel(const float2* __restrict__ xin, float2* __restrict__ out) {
    extern __shared__ ulonglong2 smU[];
    ulonglong2* SD = smU;                      // DATA_F4 entries (XP, YP packed)
    float2* TW = (float2*)(smU + DATA_F4);     // TW_F2 float2

    const int t    = threadIdx.x;
    const int lane = t & 31;
    const int w    = t >> 5;
    const int tid9 = (w << 4) | (lane >> 1) | ((lane & 1) << 8);
    const int rowA = 2 * blockIdx.x;
    const ull N1   = pack2(-1.0f, -1.0f);

    ull XP[8], YP[8];

    // --- Stage twiddles 1; load inputs packed across rows (perm ^2048) ---
    #pragma unroll
    for (int u = 0; u < 2; u++) {
        int k = 2 * (t + u * NT);              // even k: padT(k+1) == padT(k)+1
        float4 v = ((const float4*)g_tw1)[t + u * NT];
        TW[padT(k)]     = make_float2(v.x, v.y);
        TW[padT(k) + 1] = make_float2(v.z, v.w);
    }
    {
        const float4* xa4 = (const float4*)(xin + (size_t)rowA * N_FFT);
        const float4* xb4 = xa4 + N_FFT / 2;
        #pragma unroll
        for (int c = 0; c < 4; c++) {
            float4 v  = __ldg(&xa4[(4 * t + c) ^ 1024]);
            float4 vb = __ldg(&xb4[(4 * t + c) ^ 1024]);
            XP[2 * c]     = pack2(v.x, vb.x);
            YP[2 * c]     = pack2(v.y, vb.y);
            XP[2 * c + 1] = pack2(v.z, vb.z);
            YP[2 * c + 1] = pack2(v.w, vb.w);
        }
    }
    __syncthreads();   // TW1 ready

    // ================= Layer 1 =================
    stages_1_8(XP, YP, lane, TW, N1);

    // Exchange (permuted A) -> D
    #pragma unroll
    for (int n = 0; n < 8; n++)
        SD[padD(lane + 32 * cmap(n) + 256 * w)] = make_ulonglong2(XP[n], YP[n]);
    __syncthreads();
    #pragma unroll
    for (int r = 0; r < 8; r++) {
        ulonglong2 e = SD[padD(tid9 | (r << 9))];
        XP[r] = e.x; YP[r] = e.y;
    }

    stages_9_10(XP, YP, lane, tid9, TW, N1);
    stages_11_12_full(XP, YP, tid9, TW, N1);

    // ReLU (elementwise, commutes with the perm) + perm ^2048 (r ^= 4)
    #pragma unroll
    for (int r = 0; r < 8; r++) { XP[r] = relup(XP[r]); YP[r] = relup(YP[r]); }
    #pragma unroll
    for (int r = 0; r < 4; r++) {
        ull tx = XP[r]; XP[r] = XP[r + 4]; XP[r + 4] = tx;
        ull ty = YP[r]; YP[r] = YP[r + 4]; YP[r + 4] = ty;
    }

    // Exchange D -> A, swap twiddle table to layer 2
    __syncthreads();   // prior readers done
    #pragma unroll
    for (int r = 0; r < 8; r++)
        SD[padD(tid9 | (r << 9))] = make_ulonglong2(XP[r], YP[r]);
    #pragma unroll
    for (int u = 0; u < 2; u++) {
        int k = 2 * (t + u * NT);
        float4 v = ((const float4*)g_tw2)[t + u * NT];
        TW[padT(k)]     = make_float2(v.x, v.y);
        TW[padT(k) + 1] = make_float2(v.z, v.w);
    }
    __syncthreads();
    #pragma unroll
    for (int r = 0; r < 8; r++) {
        ulonglong2 e = SD[padD(8 * t + r)];
        XP[r] = e.x; YP[r] = e.y;
    }

    // ================= Layer 2 =================
    stages_1_8(XP, YP, lane, TW, N1);

    __syncthreads();   // prior A-layout readers done
    #pragma unroll
    for (int n = 0; n < 8; n++)
        SD[padD(lane + 32 * cmap(n) + 256 * w)] = make_ulonglong2(XP[n], YP[n]);
    __syncthreads();
    #pragma unroll
    for (int r = 0; r < 8; r++) {
        ulonglong2 e = SD[padD(tid9 | (r << 9))];
        XP[r] = e.x; YP[r] = e.y;
    }

    stages_9_10(XP, YP, lane, tid9, TW, N1);
    stages_11_12_trunc(XP, YP, tid9, TW, N1);

    // Output: regs r in {0,1}; row A = lo halves, row B = hi halves
    {
        float2* oa = out + (size_t)rowA * OUT_C;
        oa[tid9]               = make_float2(lo32(XP[0]), lo32(YP[0]));
        oa[tid9 + 512]         = make_float2(lo32(XP[1]), lo32(YP[1]));
        oa[OUT_C + tid9]       = make_float2(hi32(XP[0]), hi32(YP[0]));
        oa[OUT_C + tid9 + 512] = make_float2(hi32(XP[1]), hi32(YP[1]));
    }
}

extern "C" void kernel_launch(void* const* d_in, const int* in_sizes, int n_in,
                              void* d_out, int out_size) {
    const float* x  = (const float*)d_in[0];   // (4096, 8192) f32
    const float* w1 = (const float*)d_in[1];   // (2048,) f32
    const float* w2 = (const float*)d_in[2];   // (2048,) f32
    float* out = (float*)d_out;                // (4096, 2048) f32

    cudaFuncSetAttribute(mlp_fft_kernel,
                         cudaFuncAttributeMaxDynamicSharedMemorySize, SMEM_BYTES);

    twiddle_kernel<<<2, 1024>>>(w1, w2);
    mlp_fft_kernel<<<BATCH / 2, NT, SMEM_BYTES>>>((const float2*)x, (float2*)out);
}